// round 1
// baseline (speedup 1.0000x reference)
#include <cuda_runtime.h>
#include <cuda_bf16.h>

// Problem constants
#define BATCH 4
#define T 4096
#define D 1024
#define H 64
#define MTOT (BATCH * T)   // 16384 rows for projections

// GEMM tiling
#define BM 128
#define BN 128
#define BK 8

// ---------------------------------------------------------------------------
// Scratch (static __device__ globals — no allocation inside kernel_launch)
// ---------------------------------------------------------------------------
__device__ float g_QK[MTOT * 128];            //  8 MB : Q in cols [0,64), K in cols [64,128)
__device__ float g_V[(size_t)MTOT * D];       // 64 MB
__device__ float g_Wqk[128 * D];              // 0.5 MB packed [Wq; Wk]
__device__ float g_S[BATCH * T * T];          // 256 MB scores / probs

// ---------------------------------------------------------------------------
// Pack Wq (rows 0..63) and Wk (rows 64..127) into one weight matrix
// ---------------------------------------------------------------------------
__global__ void pack_qk(const float* __restrict__ Wq, const float* __restrict__ Wk,
                        float* __restrict__ Wqk) {
    int idx = blockIdx.x * 256 + threadIdx.x;     // 128*1024 = 131072 total
    if (idx < 64 * D)      Wqk[idx] = Wq[idx];
    else if (idx < 128 * D) Wqk[idx] = Wk[idx - 64 * D];
}

// ---------------------------------------------------------------------------
// C[M,N] = scale * A[M,K] * B[N,K]^T        (row-major, leading dims lda/ldb/ldc)
// blockIdx.z = batch with element strides sA/sB/sC.
// CAUSAL: skip blocks strictly above the block diagonal (used for QK^T scores).
// Tiles: 128x128x8, 256 threads, 8x8 per thread (split 4+4 raked layout).
// ---------------------------------------------------------------------------
template<bool CAUSAL>
__global__ __launch_bounds__(256)
void gemm_abt(const float* __restrict__ A, const float* __restrict__ B,
              float* __restrict__ C,
              int M, int N, int K,
              int lda, int ldb, int ldc,
              size_t sA, size_t sB, size_t sC,
              float scale) {
    const int bx = blockIdx.x, by = blockIdx.y, bz = blockIdx.z;
    if (CAUSAL && bx > by) return;   // tile fully above diagonal

    A += (size_t)bz * sA;
    B += (size_t)bz * sB;
    C += (size_t)bz * sC;

    const int row0 = by * BM;
    const int col0 = bx * BN;

    __shared__ float As[BK][BM];
    __shared__ float Bs[BK][BN];

    const int tid = threadIdx.x;
    const int tx = tid & 15;       // 0..15 -> N direction
    const int ty = tid >> 4;       // 0..15 -> M direction

    float acc[8][8];
#pragma unroll
    for (int i = 0; i < 8; i++)
#pragma unroll
        for (int j = 0; j < 8; j++) acc[i][j] = 0.f;

    // global->smem load mapping: 2 threads per row, float4 along K
    const int lrow = tid >> 1;           // 0..127
    const int lk   = (tid & 1) * 4;      // 0 or 4
    const float* Aptr = A + (size_t)(row0 + lrow) * lda + lk;
    const float* Bptr = B + (size_t)(col0 + lrow) * ldb + lk;

    for (int kk = 0; kk < K; kk += BK) {
        float4 av = *(const float4*)(Aptr + kk);
        float4 bv = *(const float4*)(Bptr + kk);
        __syncthreads();
        As[lk + 0][lrow] = av.x; As[lk + 1][lrow] = av.y;
        As[lk + 2][lrow] = av.z; As[lk + 3][lrow] = av.w;
        Bs[lk + 0][lrow] = bv.x; Bs[lk + 1][lrow] = bv.y;
        Bs[lk + 2][lrow] = bv.z; Bs[lk + 3][lrow] = bv.w;
        __syncthreads();

#pragma unroll
        for (int k = 0; k < BK; k++) {
            float a[8], b[8];
            *(float4*)(a)     = *(const float4*)&As[k][ty * 4];
            *(float4*)(a + 4) = *(const float4*)&As[k][64 + ty * 4];
            *(float4*)(b)     = *(const float4*)&Bs[k][tx * 4];
            *(float4*)(b + 4) = *(const float4*)&Bs[k][64 + tx * 4];
#pragma unroll
            for (int i = 0; i < 8; i++)
#pragma unroll
                for (int j = 0; j < 8; j++) acc[i][j] += a[i] * b[j];
        }
    }

#pragma unroll
    for (int i = 0; i < 8; i++) {
        int r = row0 + ((i < 4) ? (ty * 4 + i) : (64 + ty * 4 + i - 4));
        float4 v0 = make_float4(acc[i][0] * scale, acc[i][1] * scale,
                                acc[i][2] * scale, acc[i][3] * scale);
        float4 v1 = make_float4(acc[i][4] * scale, acc[i][5] * scale,
                                acc[i][6] * scale, acc[i][7] * scale);
        *(float4*)&C[(size_t)r * ldc + col0 + tx * 4]      = v0;
        *(float4*)&C[(size_t)r * ldc + col0 + 64 + tx * 4] = v1;
    }
}

// ---------------------------------------------------------------------------
// C[M,N] = A[M,K] * B[K,N]   (row-major). KLIMIT: causal => only k < rowTileEnd
// contributes (P is zero above diagonal), so clamp the K loop per row tile.
// ---------------------------------------------------------------------------
template<bool KLIMIT>
__global__ __launch_bounds__(256)
void gemm_ab(const float* __restrict__ A, const float* __restrict__ B,
             float* __restrict__ C,
             int M, int N, int K,
             int lda, int ldb, int ldc,
             size_t sA, size_t sB, size_t sC) {
    const int bx = blockIdx.x, by = blockIdx.y, bz = blockIdx.z;
    A += (size_t)bz * sA;
    B += (size_t)bz * sB;
    C += (size_t)bz * sC;

    const int row0 = by * BM;
    const int col0 = bx * BN;
    const int kend = KLIMIT ? min(K, (by + 1) * BM) : K;

    __shared__ float As[BK][BM];
    __shared__ float Bs[BK][BN];

    const int tid = threadIdx.x;
    const int tx = tid & 15;
    const int ty = tid >> 4;

    float acc[8][8];
#pragma unroll
    for (int i = 0; i < 8; i++)
#pragma unroll
        for (int j = 0; j < 8; j++) acc[i][j] = 0.f;

    const int arow = tid >> 1;
    const int ak   = (tid & 1) * 4;
    const float* Aptr = A + (size_t)(row0 + arow) * lda + ak;

    const int bk = tid >> 5;             // 0..7
    const int bn = (tid & 31) * 4;       // 0..124
    const float* Bptr = B + (size_t)bk * ldb + col0 + bn;

    for (int kk = 0; kk < kend; kk += BK) {
        float4 av = *(const float4*)(Aptr + kk);
        float4 bv = *(const float4*)(Bptr + (size_t)kk * ldb);
        __syncthreads();
        As[ak + 0][arow] = av.x; As[ak + 1][arow] = av.y;
        As[ak + 2][arow] = av.z; As[ak + 3][arow] = av.w;
        *(float4*)&Bs[bk][bn] = bv;
        __syncthreads();

#pragma unroll
        for (int k = 0; k < BK; k++) {
            float a[8], b[8];
            *(float4*)(a)     = *(const float4*)&As[k][ty * 4];
            *(float4*)(a + 4) = *(const float4*)&As[k][64 + ty * 4];
            *(float4*)(b)     = *(const float4*)&Bs[k][tx * 4];
            *(float4*)(b + 4) = *(const float4*)&Bs[k][64 + tx * 4];
#pragma unroll
            for (int i = 0; i < 8; i++)
#pragma unroll
                for (int j = 0; j < 8; j++) acc[i][j] += a[i] * b[j];
        }
    }

#pragma unroll
    for (int i = 0; i < 8; i++) {
        int r = row0 + ((i < 4) ? (ty * 4 + i) : (64 + ty * 4 + i - 4));
        *(float4*)&C[(size_t)r * ldc + col0 + tx * 4]      = *(float4*)&acc[i][0];
        *(float4*)&C[(size_t)r * ldc + col0 + 64 + tx * 4] = *(float4*)&acc[i][4];
    }
}

// ---------------------------------------------------------------------------
// Causal row softmax in-place on S[b, i, :]. One block per (row, batch).
// Row held in registers (16 floats/thread). Writes zeros for j > i so the
// P @ V GEMM can run unmasked.
// ---------------------------------------------------------------------------
__global__ __launch_bounds__(256)
void softmax_rows(float* __restrict__ S) {
    const int i = blockIdx.x;
    const int b = blockIdx.y;
    float* row = S + ((size_t)b * T + i) * (size_t)T;
    const int tid = threadIdx.x;
    const int len = i + 1;

    constexpr int R = T / 256;  // 16
    float local[R];
    float m = -3.4e38f;
#pragma unroll
    for (int r = 0; r < R; r++) {
        int j = r * 256 + tid;
        float v = (j < len) ? row[j] : -3.4e38f;
        local[r] = v;
        m = fmaxf(m, v);
    }

    __shared__ float red[8];
#pragma unroll
    for (int o = 16; o; o >>= 1) m = fmaxf(m, __shfl_xor_sync(0xffffffffu, m, o));
    if ((tid & 31) == 0) red[tid >> 5] = m;
    __syncthreads();
    m = red[0];
#pragma unroll
    for (int w = 1; w < 8; w++) m = fmaxf(m, red[w]);
    __syncthreads();

    float s = 0.f;
#pragma unroll
    for (int r = 0; r < R; r++) {
        int j = r * 256 + tid;
        float e = (j < len) ? __expf(local[r] - m) : 0.f;
        local[r] = e;
        s += e;
    }
#pragma unroll
    for (int o = 16; o; o >>= 1) s += __shfl_xor_sync(0xffffffffu, s, o);
    if ((tid & 31) == 0) red[tid >> 5] = s;
    __syncthreads();
    s = red[0];
#pragma unroll
    for (int w = 1; w < 8; w++) s += red[w];

    const float inv = 1.f / s;
#pragma unroll
    for (int r = 0; r < R; r++) {
        int j = r * 256 + tid;
        row[j] = local[r] * inv;
    }
}

// ---------------------------------------------------------------------------
// kernel_launch: pack -> QK proj -> V proj -> scores -> softmax -> P@V
// ---------------------------------------------------------------------------
extern "C" void kernel_launch(void* const* d_in, const int* in_sizes, int n_in,
                              void* d_out, int out_size) {
    const float* x  = (const float*)d_in[0];
    const float* Wk = (const float*)d_in[1];
    const float* Wq = (const float*)d_in[2];
    const float* Wv = (const float*)d_in[3];
    float* out = (float*)d_out;

    float *qk, *v, *wqk, *s;
    cudaGetSymbolAddress((void**)&qk,  g_QK);
    cudaGetSymbolAddress((void**)&v,   g_V);
    cudaGetSymbolAddress((void**)&wqk, g_Wqk);
    cudaGetSymbolAddress((void**)&s,   g_S);

    // 1) pack [Wq; Wk] -> 128 x 1024
    pack_qk<<<(128 * D + 255) / 256, 256>>>(Wq, Wk, wqk);

    // 2) QK projection: [16384,1024] x [128,1024]^T -> g_QK [16384,128]
    gemm_abt<false><<<dim3(1, MTOT / BM, 1), 256>>>(
        x, wqk, qk, MTOT, 128, D, D, D, 128, 0, 0, 0, 1.0f);

    // 3) V projection: [16384,1024] x [1024,1024]^T -> g_V
    gemm_abt<false><<<dim3(D / BN, MTOT / BM, 1), 256>>>(
        x, Wv, v, MTOT, D, D, D, D, D, 0, 0, 0, 1.0f);

    // 4) scores: S[b] = (Q K^T) / 8, causal block-skip
    gemm_abt<true><<<dim3(T / BN, T / BM, BATCH), 256>>>(
        qk,            // Q: cols [0,64)
        qk + 64,       // K: cols [64,128)
        s,
        T, T, H, 128, 128, T,
        (size_t)T * 128, (size_t)T * 128, (size_t)T * T,
        0.125f);       // 1/sqrt(64)

    // 5) causal softmax rows (writes zeros above the diagonal)
    softmax_rows<<<dim3(T, BATCH), 256>>>(s);

    // 6) out[b] = P[b] @ V[b], causal K-limit per row tile
    gemm_ab<true><<<dim3(D / BN, T / BM, BATCH), 256>>>(
        s, v, out, T, D, T, T, D, D,
        (size_t)T * T, (size_t)T * D, (size_t)T * D);
}

// round 5
// speedup vs baseline: 1.6069x; 1.6069x over previous
#include <cuda_runtime.h>
#include <cuda_bf16.h>
#include <cstdint>

#define BATCH 4
#define T 4096
#define D 1024
#define H 64
#define MTOT (BATCH * T)

// ---------------------------------------------------------------------------
// Scratch (__device__ globals; no allocation in kernel_launch)
// 3-term bf16 split, chunk-interleaved per 64 source cols (K' = 3K):
//   A-side chunk layout: [hi | hi | lo]
//   B-side chunk layout: [hi | lo | hi]
//   => A'.B'^T = Ahi.Bhi + Ahi.Blo + Alo.Bhi
// ---------------------------------------------------------------------------
__device__ __align__(256) __nv_bfloat16 g_xA[(size_t)MTOT * 3 * D];      // 96 MB
__device__ __align__(256) __nv_bfloat16 g_xB[(size_t)MTOT * 3 * D];      // 96 MB
__device__ __align__(256) __nv_bfloat16 g_wqkB[128 * 3 * D];             // .75 MB
__device__ __align__(256) __nv_bfloat16 g_wvA[(size_t)D * 3 * D];        // 6 MB
__device__ __align__(256) float        g_qk[(size_t)MTOT * 128];         // 8 MB
__device__ __align__(256) __nv_bfloat16 g_qA[(size_t)MTOT * 192];        // 6 MB
__device__ __align__(256) __nv_bfloat16 g_kB[(size_t)MTOT * 192];        // 6 MB
__device__ __align__(256) float        g_vt[(size_t)D * MTOT];           // 64 MB (V^T)
__device__ __align__(256) __nv_bfloat16 g_vtB[(size_t)BATCH * D * 3 * T];// 96 MB
__device__ __align__(256) float        g_S[(size_t)BATCH * T * T];       // 256 MB
__device__ __align__(256) __nv_bfloat16 g_pA[(size_t)BATCH * T * 3 * T]; // 384 MB

// ---------------------------------------------------------------------------
// Pack kernels
// ---------------------------------------------------------------------------
__global__ __launch_bounds__(256) void pack_x(const float* __restrict__ x,
                                              __nv_bfloat16* __restrict__ xA,
                                              __nv_bfloat16* __restrict__ xB) {
    int idx = blockIdx.x * 256 + threadIdx.x;
    if (idx >= MTOT * D) return;
    int row = idx >> 10;
    int k = idx & 1023;
    float v = x[idx];
    __nv_bfloat16 hi = __float2bfloat16(v);
    __nv_bfloat16 lo = __float2bfloat16(v - __bfloat162float(hi));
    int c = k >> 6, o = k & 63;
    size_t base = (size_t)row * 3072 + c * 192 + o;
    xA[base] = hi; xA[base + 64] = hi; xA[base + 128] = lo;
    xB[base] = hi; xB[base + 64] = lo; xB[base + 128] = hi;
}

// layB=0: A layout [hi|hi|lo]; layB=1: B layout [hi|lo|hi]
__global__ __launch_bounds__(256) void pack_split(const float* __restrict__ src, int ldsrc,
                                                  int col0, int ncols,
                                                  __nv_bfloat16* __restrict__ dst,
                                                  int layB, float scale, int total) {
    int idx = blockIdx.x * 256 + threadIdx.x;
    if (idx >= total) return;
    int row = idx / ncols;
    int k = idx - row * ncols;
    float v = src[(size_t)row * ldsrc + col0 + k] * scale;
    __nv_bfloat16 hi = __float2bfloat16(v);
    __nv_bfloat16 lo = __float2bfloat16(v - __bfloat162float(hi));
    int c = k >> 6, o = k & 63;
    size_t base = (size_t)row * (3 * ncols) + c * 192 + o;
    dst[base] = hi;
    dst[base + 64]  = layB ? lo : hi;
    dst[base + 128] = layB ? hi : lo;
}

// ---------------------------------------------------------------------------
// HMMA (mma.sync) GEMM: C[M,N] = A'[M,K'] * B'[N,K']^T  (both K-contiguous)
// 128x128x32 CTA tile, 8 warps as 4(M)x2(N), warp tile 32x64.
// cp.async double-buffered smem, 80B padded rows (conflict-free ldmatrix).
// CAUSAL: skip tiles bx > by.  KLIMIT: nc = 12*(by+1) chunks (P@V causal).
// ---------------------------------------------------------------------------
#define ASTRIDE 80           // bytes per 32-bf16 smem row (64B data + 16B pad)
#define TILE_BYTES (128 * ASTRIDE)          // 10240
#define STAGE_BYTES (2 * TILE_BYTES)        // A + B

__device__ __forceinline__ uint32_t smem_u32(const void* p) {
    uint32_t a;
    asm("{ .reg .u64 t; cvta.to.shared.u64 t, %1; cvt.u32.u64 %0, t; }" : "=r"(a) : "l"(p));
    return a;
}
__device__ __forceinline__ void cp16(uint32_t dst, const void* src) {
    asm volatile("cp.async.cg.shared.global [%0], [%1], 16;" :: "r"(dst), "l"(src));
}
__device__ __forceinline__ void ldm_x4(uint32_t* r, uint32_t addr) {
    asm volatile("ldmatrix.sync.aligned.m8n8.x4.shared.b16 {%0,%1,%2,%3}, [%4];"
                 : "=r"(r[0]), "=r"(r[1]), "=r"(r[2]), "=r"(r[3]) : "r"(addr));
}
__device__ __forceinline__ void mma16816(float* d, const uint32_t* a, const uint32_t* b) {
    asm volatile(
        "mma.sync.aligned.m16n8k16.row.col.f32.bf16.bf16.f32 "
        "{%0,%1,%2,%3}, {%4,%5,%6,%7}, {%8,%9}, {%0,%1,%2,%3};"
        : "+f"(d[0]), "+f"(d[1]), "+f"(d[2]), "+f"(d[3])
        : "r"(a[0]), "r"(a[1]), "r"(a[2]), "r"(a[3]), "r"(b[0]), "r"(b[1]));
}

template<bool CAUSAL, bool KLIMIT>
__global__ __launch_bounds__(256)
void gemm_hmma(const __nv_bfloat16* __restrict__ A, const __nv_bfloat16* __restrict__ B,
               float* __restrict__ C, int lda, int ldb, int ldc, int NC,
               size_t sA, size_t sB, size_t sC) {
    const int bx = blockIdx.x, by = blockIdx.y, bz = blockIdx.z;
    if (CAUSAL && bx > by) return;
    A += (size_t)bz * sA;
    B += (size_t)bz * sB;
    C += (size_t)bz * sC;
    const int row0 = by * 128, col0 = bx * 128;
    const int nc = KLIMIT ? min(NC, 12 * (by + 1)) : NC;

    __shared__ __align__(128) char smem[2 * STAGE_BYTES];   // 40 KB
    const uint32_t sbase = smem_u32(smem);

    const int tid = threadIdx.x;
    const int lane = tid & 31;
    const int w = tid >> 5;
    const int wm = (w & 3) * 32;       // warp m offset in tile
    const int wn = (w >> 2) * 64;      // warp n offset in tile

    // ---- cp.async mapping: thread -> (row, 32B half of the 64B row) ----
    const int lr = tid >> 1;                 // 0..127
    const int lh = (tid & 1);                // 0/1 -> byte offset 0/32
    const __nv_bfloat16* Ap = A + (size_t)(row0 + lr) * lda + lh * 16;
    const __nv_bfloat16* Bp = B + (size_t)(col0 + lr) * ldb + lh * 16;
    const uint32_t dstRow = lr * ASTRIDE + lh * 32;

    // ---- ldmatrix base addresses (per warp) ----
    // A x4: lanes0-7 rows m0..7 kh0 | 8-15 rows m8..15 kh0 | 16-23 m0..7 kh1 | 24-31 m8..15 kh1
    uint32_t aoff[2];
#pragma unroll
    for (int mt = 0; mt < 2; mt++)
        aoff[mt] = (uint32_t)((wm + mt * 16 + (lane & 15)) * ASTRIDE + ((lane >> 4) * 16));
    // B x4: lanes0-7 rows n0..7 kh0 | 8-15 n0..7 kh1 | 16-23 n8..15 kh0 | 24-31 n8..15 kh1
    uint32_t boff[4];
#pragma unroll
    for (int nt2 = 0; nt2 < 4; nt2++)
        boff[nt2] = (uint32_t)((wn + nt2 * 16 + (lane & 7) + ((lane >> 4) & 1) * 8) * ASTRIDE
                               + (((lane >> 3) & 1) * 16));

    float acc[2][8][4];
#pragma unroll
    for (int mt = 0; mt < 2; mt++)
#pragma unroll
        for (int nt = 0; nt < 8; nt++)
#pragma unroll
            for (int q = 0; q < 4; q++) acc[mt][nt][q] = 0.f;

    // ---- prologue: load chunk 0 into stage 0 ----
    {
        uint32_t ad = sbase + dstRow;
        uint32_t bd = sbase + TILE_BYTES + dstRow;
        cp16(ad, Ap);       cp16(ad + 16, Ap + 8);
        cp16(bd, Bp);       cp16(bd + 16, Bp + 8);
        asm volatile("cp.async.commit_group;" ::: "memory");
    }

    int buf = 0;
    for (int kc = 0; kc < nc; kc++) {
        if (kc + 1 < nc) {
            const __nv_bfloat16* a2 = Ap + (size_t)(kc + 1) * 32;
            const __nv_bfloat16* b2 = Bp + (size_t)(kc + 1) * 32;
            uint32_t st = sbase + (buf ^ 1) * STAGE_BYTES;
            cp16(st + dstRow, a2);                    cp16(st + dstRow + 16, a2 + 8);
            cp16(st + TILE_BYTES + dstRow, b2);       cp16(st + TILE_BYTES + dstRow + 16, b2 + 8);
            asm volatile("cp.async.commit_group;" ::: "memory");
            asm volatile("cp.async.wait_group 1;" ::: "memory");
        } else {
            asm volatile("cp.async.wait_group 0;" ::: "memory");
        }
        __syncthreads();

        const uint32_t abase = sbase + buf * STAGE_BYTES;
        const uint32_t bbase = abase + TILE_BYTES;
#pragma unroll
        for (int k16 = 0; k16 < 2; k16++) {
            const uint32_t ko = k16 * 32;
            uint32_t afr[2][4];
            ldm_x4(afr[0], abase + aoff[0] + ko);
            ldm_x4(afr[1], abase + aoff[1] + ko);
            uint32_t bfr[8][2];
#pragma unroll
            for (int nt2 = 0; nt2 < 4; nt2++) {
                uint32_t r[4];
                ldm_x4(r, bbase + boff[nt2] + ko);
                bfr[2 * nt2][0] = r[0]; bfr[2 * nt2][1] = r[1];
                bfr[2 * nt2 + 1][0] = r[2]; bfr[2 * nt2 + 1][1] = r[3];
            }
#pragma unroll
            for (int mt = 0; mt < 2; mt++)
#pragma unroll
                for (int nt = 0; nt < 8; nt++)
                    mma16816(acc[mt][nt], afr[mt], bfr[nt]);
        }
        __syncthreads();
        buf ^= 1;
    }

    // ---- epilogue ----
    const int rq = lane >> 2;          // 0..7
    const int cq = (lane & 3) * 2;
#pragma unroll
    for (int mt = 0; mt < 2; mt++) {
#pragma unroll
        for (int nt = 0; nt < 8; nt++) {
            float* p = C + (size_t)(row0 + wm + mt * 16 + rq) * ldc + col0 + wn + nt * 8 + cq;
            p[0] = acc[mt][nt][0];
            p[1] = acc[mt][nt][1];
            float* p2 = p + 8 * (size_t)ldc;
            p2[0] = acc[mt][nt][2];
            p2[1] = acc[mt][nt][3];
        }
    }
}

// ---------------------------------------------------------------------------
// Causal softmax: reads fp32 scores row, writes split-bf16 P (A layout)
// ---------------------------------------------------------------------------
__global__ __launch_bounds__(256)
void softmax_split(const float* __restrict__ S, __nv_bfloat16* __restrict__ P) {
    const int i = blockIdx.x;
    const int b = blockIdx.y;
    const float* row = S + ((size_t)b * T + i) * (size_t)T;
    __nv_bfloat16* prow = P + ((size_t)b * T + i) * (size_t)(3 * T);
    const int tid = threadIdx.x;
    const int len = i + 1;

    constexpr int R = T / 256;
    float local[R];
    float m = -3.4e38f;
#pragma unroll
    for (int r = 0; r < R; r++) {
        int j = r * 256 + tid;
        float v = (j < len) ? row[j] : -3.4e38f;
        local[r] = v;
        m = fmaxf(m, v);
    }
    __shared__ float red[8];
#pragma unroll
    for (int o = 16; o; o >>= 1) m = fmaxf(m, __shfl_xor_sync(0xffffffffu, m, o));
    if ((tid & 31) == 0) red[tid >> 5] = m;
    __syncthreads();
    m = red[0];
#pragma unroll
    for (int w = 1; w < 8; w++) m = fmaxf(m, red[w]);
    __syncthreads();

    float s = 0.f;
#pragma unroll
    for (int r = 0; r < R; r++) {
        int j = r * 256 + tid;
        float e = (j < len) ? __expf(local[r] - m) : 0.f;
        local[r] = e;
        s += e;
    }
#pragma unroll
    for (int o = 16; o; o >>= 1) s += __shfl_xor_sync(0xffffffffu, s, o);
    if ((tid & 31) == 0) red[tid >> 5] = s;
    __syncthreads();
    s = red[0];
#pragma unroll
    for (int w = 1; w < 8; w++) s += red[w];

    const float inv = 1.f / s;
#pragma unroll
    for (int r = 0; r < R; r++) {
        int j = r * 256 + tid;
        float p = local[r] * inv;
        __nv_bfloat16 hi = __float2bfloat16(p);
        __nv_bfloat16 lo = __float2bfloat16(p - __bfloat162float(hi));
        int c = j >> 6, o2 = j & 63;
        size_t base = (size_t)c * 192 + o2;
        prow[base] = hi; prow[base + 64] = hi; prow[base + 128] = lo;
    }
}

// ---------------------------------------------------------------------------
// kernel_launch
// ---------------------------------------------------------------------------
extern "C" void kernel_launch(void* const* d_in, const int* in_sizes, int n_in,
                              void* d_out, int out_size) {
    const float* x  = (const float*)d_in[0];
    const float* Wk = (const float*)d_in[1];
    const float* Wq = (const float*)d_in[2];
    const float* Wv = (const float*)d_in[3];
    float* out = (float*)d_out;

    __nv_bfloat16 *xA, *xB, *wqkB, *wvA, *qA, *kB, *vtB, *pA;
    float *qk, *vt, *S;
    cudaGetSymbolAddress((void**)&xA, g_xA);
    cudaGetSymbolAddress((void**)&xB, g_xB);
    cudaGetSymbolAddress((void**)&wqkB, g_wqkB);
    cudaGetSymbolAddress((void**)&wvA, g_wvA);
    cudaGetSymbolAddress((void**)&qk, g_qk);
    cudaGetSymbolAddress((void**)&qA, g_qA);
    cudaGetSymbolAddress((void**)&kB, g_kB);
    cudaGetSymbolAddress((void**)&vt, g_vt);
    cudaGetSymbolAddress((void**)&vtB, g_vtB);
    cudaGetSymbolAddress((void**)&S, g_S);
    cudaGetSymbolAddress((void**)&pA, g_pA);

    // 1) input packs
    pack_x<<<(MTOT * D + 255) / 256, 256>>>(x, xA, xB);
    pack_split<<<(64 * D + 255) / 256, 256>>>(Wq, D, 0, D, wqkB, 1, 1.f, 64 * D);
    pack_split<<<(64 * D + 255) / 256, 256>>>(Wk, D, 0, D, wqkB + (size_t)64 * 3 * D, 1, 1.f, 64 * D);
    pack_split<<<(D * D + 255) / 256, 256>>>(Wv, D, 0, D, wvA, 0, 1.f, D * D);

    // 2) QK projection: [16384,3072] x [128,3072]^T -> qk fp32 [16384,128]
    gemm_hmma<false, false><<<dim3(1, MTOT / 128, 1), 256>>>(
        xA, wqkB, qk, 3 * D, 3 * D, 128, 96, 0, 0, 0);

    // 3) V^T projection: Wv[1024,3072] x X[16384,3072]^T -> vt fp32 [1024,16384]
    gemm_hmma<false, false><<<dim3(MTOT / 128, D / 128, 1), 256>>>(
        wvA, xB, vt, 3 * D, 3 * D, MTOT, 96, 0, 0, 0);

    // 4) split-pack Q (pre-scaled 1/8), K, V^T
    pack_split<<<(MTOT * 64 + 255) / 256, 256>>>(qk, 128, 0, 64, qA, 0, 0.125f, MTOT * 64);
    pack_split<<<(MTOT * 64 + 255) / 256, 256>>>(qk, 128, 64, 64, kB, 1, 1.f, MTOT * 64);
    for (int b = 0; b < BATCH; b++) {
        pack_split<<<(D * T + 255) / 256, 256>>>(
            vt, MTOT, b * T, T, vtB + (size_t)b * D * 3 * T, 1, 1.f, D * T);
    }

    // 5) scores: S[b] = Qs K^T (causal tile skip)
    gemm_hmma<true, false><<<dim3(T / 128, T / 128, BATCH), 256>>>(
        qA, kB, S, 192, 192, T, 6,
        (size_t)T * 192, (size_t)T * 192, (size_t)T * T);

    // 6) softmax -> split P
    softmax_split<<<dim3(T, BATCH), 256>>>(S, pA);

    // 7) out[b] = P[b] @ V[b]  (= P * Vt^T), causal K-limit
    gemm_hmma<false, true><<<dim3(D / 128, T / 128, BATCH), 256>>>(
        pA, vtB, out, 3 * T, 3 * T, D, 384,
        (size_t)T * 3 * T, (size_t)D * 3 * T, (size_t)T * D);
}